// round 1
// baseline (speedup 1.0000x reference)
#include <cuda_runtime.h>
#include <cuda_fp16.h>
#include <math.h>

#define N_PIX (768*768)          // 589824 pixels
#define D     256
#define C     21
#define P     64                 // pixels per tile
#define NTILES (N_PIX / P)       // 9216
#define TPB   512
#define GRID  148

// ---------------- global scratch (static, no allocation) ----------------
__device__ float g_sums[C * D];
__device__ int   g_counts[C];

// ---------------- cp.async helpers ----------------
__device__ __forceinline__ void cpa16(void* s, const void* g) {
    unsigned sa = (unsigned)__cvta_generic_to_shared(s);
    asm volatile("cp.async.cg.shared.global [%0], [%1], 16;\n" :: "r"(sa), "l"(g));
}
__device__ __forceinline__ void cpa_commit() { asm volatile("cp.async.commit_group;\n"); }
template<int n> __device__ __forceinline__ void cpa_wait() {
    asm volatile("cp.async.wait_group %0;\n" :: "n"(n));
}

// ---------------- kernel 0: zero accumulators ----------------
__global__ void zero_kernel() {
    int i = blockIdx.x * blockDim.x + threadIdx.x;
    if (i < C * D) g_sums[i] = 0.f;
    if (i < C)     g_counts[i] = 0;
}

// ---------------- smem layout (dynamic) ----------------
// buf   : 2 * D * P floats   (131072 B)  double-buffered tile [d][64]
// slab  : 2 * P ints         (512 B)     double-buffered labels
// acc   : 2 * C * D floats   (43008 B)   two accumulator copies (one per thread-set)
// nred  : TPB floats         (2048 B)
// aux   : P  u32             (256 B)     packed (lab*D)<<16 | half(invnorm)
// scnt  : C ints             (96 B)
#define SM_BUF   0
#define SM_SLAB  (2*D*P)                 // in floats
#define SM_ACC   (SM_SLAB + 2*P)
#define SM_NRED  (SM_ACC + 2*C*D)
#define SM_AUX   (SM_NRED + TPB)
#define SM_SCNT  (SM_AUX + P)
#define SM_TOTAL_FLOATS (SM_SCNT + 32)
#define SMEM_BYTES (SM_TOTAL_FLOATS * 4)

__device__ __forceinline__ void prefetch_tile(const float* __restrict__ feat,
                                              const int* __restrict__ lab,
                                              float* buf, int* slab,
                                              int b, int tile, int t) {
    const int p0 = tile * P;
    float* dst = buf + b * (D * P);
    #pragma unroll
    for (int k = 0; k < 8; k++) {
        int j  = k * TPB + t;        // 0..4095 float4 chunks
        int d  = j >> 4;             // dim row (64 floats = 16 float4 per row)
        int c4 = (j & 15) << 2;      // float offset in row
        cpa16(dst + d * P + c4, feat + (size_t)d * N_PIX + p0 + c4);
    }
    if (t < 16) cpa16(slab + b * P + t * 4, lab + p0 + t * 4);
}

// ---------------- kernel 1: normalize + class scatter-sum ----------------
__global__ __launch_bounds__(TPB, 1)
void accum_kernel(const float* __restrict__ feat, const int* __restrict__ lab) {
    extern __shared__ float smem[];
    float*    buf  = smem + SM_BUF;
    int*      slab = (int*)(smem + SM_SLAB);
    float*    acc  = smem + SM_ACC;
    float*    nred = smem + SM_NRED;
    unsigned* aux  = (unsigned*)(smem + SM_AUX);
    int*      scnt = (int*)(smem + SM_SCNT);

    const int t = threadIdx.x;

    for (int i = t; i < 2 * C * D; i += TPB) acc[i] = 0.f;
    if (t < C) scnt[t] = 0;
    __syncthreads();

    int tl = blockIdx.x;
    prefetch_tile(feat, lab, buf, slab, 0, tl, t);
    cpa_commit();

    int cur = 0;
    const int dim = t & (D - 1);     // 0..255
    const int s   = t >> 8;          // thread-set 0/1
    float* ac = acc + s * (C * D);

    for (; tl < NTILES; tl += GRID) {
        int nxt = tl + GRID;
        if (nxt < NTILES) prefetch_tile(feat, lab, buf, slab, cur ^ 1, nxt, t);
        cpa_commit();
        cpa_wait<1>();               // current tile's group complete
        __syncthreads();

        const float* tbase = buf + cur * (D * P);
        const int*   lb    = slab + cur * P;

        // ---- per-pixel sum of squares: 8 threads per pixel, 32 dims each ----
        {
            int p = t & (P - 1);
            int q = t >> 6;          // 0..7
            float ss = 0.f;
            #pragma unroll
            for (int dd = 0; dd < 32; dd++) {
                float v = tbase[(q * 32 + dd) * P + p];
                ss += v * v;
            }
            nred[t] = ss;
        }
        __syncthreads();
        if (t < P) {
            float ss = 0.f;
            #pragma unroll
            for (int q = 0; q < 8; q++) ss += nred[q * P + t];
            float inv = 1.0f / fmaxf(sqrtf(ss), 1e-12f);
            int labv = lb[t];
            aux[t] = ((unsigned)(labv * D) << 16) |
                     (unsigned)__half_as_ushort(__float2half_rn(inv));
            atomicAdd(&scnt[labv], 1);
        }
        __syncthreads();

        // ---- scatter-accumulate: thread owns dim `dim`, set s owns 32 pixels ----
        {
            const float* tb = tbase + dim * P;
            #pragma unroll 8
            for (int i = 0; i < 32; i++) {
                int p = ((dim + i) & 31) | (s << 5);      // lane-staggered, conflict-free
                unsigned a = aux[p];
                float w = __half2float(__ushort_as_half((unsigned short)(a & 0xffffu)));
                int cb = (int)(a >> 16);                   // lab * D
                ac[cb + dim] += tb[p] * w;
            }
        }
        __syncthreads();
        cur ^= 1;
    }

    // ---- flush per-block partials once ----
    cpa_wait<0>();
    for (int i = t; i < C * D; i += TPB)
        atomicAdd(&g_sums[i], acc[i] + acc[C * D + i]);
    if (t < C) atomicAdd(&g_counts[t], scnt[t]);
}

// ---------------- kernel 2: means -> logits -> loss ----------------
__global__ void finalize_kernel(const float* __restrict__ proto, float* __restrict__ out) {
    __shared__ float s_mean[C * D];
    __shared__ float s_proto[C * D];
    __shared__ float s_logit[C * C];
    const int t = threadIdx.x;     // 672 threads = 21 warps

    for (int i = t; i < C * D; i += blockDim.x) {
        int c = i / D;
        float cnt = (float)g_counts[c];
        s_mean[i]  = g_sums[i] / fmaxf(cnt, 1.0f);
        s_proto[i] = proto[i];
    }
    __syncthreads();

    int w = t >> 5, l = t & 31;
    if (w < C) {
        for (int j = 0; j < C; j++) {
            float sacc = 0.f;
            #pragma unroll
            for (int k = 0; k < 8; k++)
                sacc += s_mean[w * D + l + 32 * k] * s_proto[j * D + l + 32 * k];
            #pragma unroll
            for (int o = 16; o; o >>= 1) sacc += __shfl_xor_sync(0xffffffffu, sacc, o);
            if (l == 0) s_logit[w * C + j] = sacc * 10.0f;   // / TEMP (0.1)
        }
    }
    __syncthreads();

    if (t < 32) {
        float v = 0.f;
        if (t >= 1 && t < C) {
            float mx = -INFINITY;
            for (int j = 0; j < C; j++) mx = fmaxf(mx, s_logit[t * C + j]);
            float den = 0.f;
            for (int j = 1; j < C; j++) den += expf(s_logit[t * C + j] - mx);
            v = logf(den) - (s_logit[t * C + t] - mx);
        }
        #pragma unroll
        for (int o = 16; o; o >>= 1) v += __shfl_xor_sync(0xffffffffu, v, o);
        if (t == 0) out[0] = v / (float)(C - 1);
    }
}

// ---------------- launch ----------------
extern "C" void kernel_launch(void* const* d_in, const int* in_sizes, int n_in,
                              void* d_out, int out_size) {
    const float* feat  = (const float*)d_in[0];   // [1,256,768,768]
    const float* proto = (const float*)d_in[1];   // [21,256]
    // d_in[2] = outputs (unused by the loss)
    const int*   lab   = (const int*)d_in[3];     // [1,1,768,768]
    float* out = (float*)d_out;

    cudaFuncSetAttribute(accum_kernel,
                         cudaFuncAttributeMaxDynamicSharedMemorySize, SMEM_BYTES);

    zero_kernel<<<(C * D + 255) / 256, 256>>>();
    accum_kernel<<<GRID, TPB, SMEM_BYTES>>>(feat, lab);
    finalize_kernel<<<1, 672>>>(proto, out);
}